// round 2
// baseline (speedup 1.0000x reference)
#include <cuda_runtime.h>
#include <math.h>
#include <stdint.h>

#define BB 64
#define SS 512
#define FF 128
#define HH 512
#define G4 2048
#define NCTA 128
#define TPB 256
#define HP 516            // hs pitch in floats (conflict-free)

// Scratch (static device globals — no allocation at kernel_launch time)
__device__ float g_xg[(size_t)SS * BB * G4];    // [S][B][4H] precomputed input gates
__device__ float g_hist[(size_t)SS * BB * HH];  // [S][B][H] hidden state history
__device__ unsigned g_cnt[SS];                  // per-step arrival counters

// packed dual-fp32 FMA (Blackwell f32x2)
#define FMA2(acc, a, h) asm("fma.rn.f32x2 %0, %1, %2, %0;" : "+l"(acc) : "l"(a), "l"(h))

__device__ __forceinline__ float rsum2(unsigned long long v) {
    float lo, hi;
    asm("mov.b64 {%0,%1}, %2;" : "=f"(lo), "=f"(hi) : "l"(v));
    return lo + hi;
}

__global__ void init_kernel() {
    int i = blockIdx.x * blockDim.x + threadIdx.x;
    if (i < SS) g_cnt[i] = 0;
}

// ---------------------------------------------------------------------------
// x_gates GEMM: C[m=(s,b)][g] = sum_f inputs[b,s,f]*W_ih[g,f] + b_ih[g]+b_hh[g]
// ---------------------------------------------------------------------------
__global__ __launch_bounds__(256) void xg_kernel(
    const float* __restrict__ inp, const float* __restrict__ Wih,
    const float* __restrict__ bih, const float* __restrict__ bhh)
{
    __shared__ float As[32][68];
    __shared__ float Bs[32][68];
    const int gBase = blockIdx.x * 64;
    const int mBase = blockIdx.y * 64;
    const int t = threadIdx.x;
    const int tx = t & 15, ty = t >> 4;

    float acc[4][4] = {};

    for (int k0 = 0; k0 < FF; k0 += 32) {
        #pragma unroll
        for (int it = 0; it < 2; it++) {
            int idx = t + it * 256;
            int row = idx >> 3, vec = idx & 7;
            int m = mBase + row;
            int b = m & 63, s = m >> 6;
            float4 v = *(const float4*)(inp + ((size_t)b * SS + s) * FF + k0 + vec * 4);
            As[vec * 4 + 0][row] = v.x; As[vec * 4 + 1][row] = v.y;
            As[vec * 4 + 2][row] = v.z; As[vec * 4 + 3][row] = v.w;
        }
        #pragma unroll
        for (int it = 0; it < 2; it++) {
            int idx = t + it * 256;
            int row = idx >> 3, vec = idx & 7;
            float4 v = *(const float4*)(Wih + (size_t)(gBase + row) * FF + k0 + vec * 4);
            Bs[vec * 4 + 0][row] = v.x; Bs[vec * 4 + 1][row] = v.y;
            Bs[vec * 4 + 2][row] = v.z; Bs[vec * 4 + 3][row] = v.w;
        }
        __syncthreads();
        #pragma unroll
        for (int kk = 0; kk < 32; kk++) {
            float a[4], b[4];
            *(float4*)a = *(const float4*)&As[kk][ty * 4];
            *(float4*)b = *(const float4*)&Bs[kk][tx * 4];
            #pragma unroll
            for (int i = 0; i < 4; i++)
                #pragma unroll
                for (int jj = 0; jj < 4; jj++)
                    acc[i][jj] += a[i] * b[jj];
        }
        __syncthreads();
    }

    float bias[4];
    #pragma unroll
    for (int jj = 0; jj < 4; jj++) {
        int g = gBase + tx * 4 + jj;
        bias[jj] = bih[g] + bhh[g];
    }
    #pragma unroll
    for (int i = 0; i < 4; i++) {
        int m = mBase + ty * 4 + i;
        float4 o;
        o.x = acc[i][0] + bias[0];
        o.y = acc[i][1] + bias[1];
        o.z = acc[i][2] + bias[2];
        o.w = acc[i][3] + bias[3];
        *(float4*)(g_xg + (size_t)m * G4 + gBase + tx * 4) = o;
    }
}

// ---------------------------------------------------------------------------
// Persistent LSTM: 128 CTAs, each owns 4 hidden units (x4 gates) x 64 batches.
// W slice resident in SMEM; h broadcast via cp.async each step; grid barrier.
// ---------------------------------------------------------------------------
__global__ __launch_bounds__(TPB, 1) void lstm_persist(const float* __restrict__ Whh)
{
    extern __shared__ float smem[];
    float* ws = smem;             // 16 rows x 512 = 8192 floats (32 KB)
    float* hs = smem + 8192;      // 64 rows x HP floats (129 KB)

    const int t = threadIdx.x;
    const int w = t >> 5, l = t & 31;
    const int j = l >> 3;               // 0..3 (unit within CTA)
    const int b = (l & 7) + (w << 3);   // 0..63
    const int j0 = blockIdx.x << 2;
    const int jg = j0 + j;

    // Load W slice once: ws[(jj*4+g)*512 + k] = Whh[g*HH + j0+jj][k]
    #pragma unroll
    for (int r = 0; r < 8; r++) {
        int f4 = t + (r << 8);           // 0..2047 float4 chunks
        int row = f4 >> 7;               // 0..15 = jj*4+g
        int col = (f4 & 127) << 2;
        int jj = row >> 2, g = row & 3;
        *(float4*)&ws[(row << 9) + col] =
            *(const float4*)&Whh[((size_t)(g * HH + j0 + jj) << 9) + col];
    }
    __syncthreads();

    const float* wp0 = ws + ((j * 4 + 0) << 9);
    const float* wp1 = ws + ((j * 4 + 1) << 9);
    const float* wp2 = ws + ((j * 4 + 2) << 9);
    const float* wp3 = ws + ((j * 4 + 3) << 9);
    const float* hb  = hs + b * HP;

    float c = 0.f;

    for (int s = 0; s < SS; s++) {
        const size_t xb = (((size_t)s << 6) + b) * G4 + jg;
        float a0 = g_xg[xb];
        float a1 = g_xg[xb + 512];
        float a2 = g_xg[xb + 1024];
        float a3 = g_xg[xb + 1536];

        if (s > 0) {
            if (t == 0) {
                while (*((volatile unsigned*)&g_cnt[s - 1]) < NCTA) { }
            }
            __syncthreads();

            const float* hp = g_hist + ((size_t)(s - 1) << 15);  // * BB*HH

            // phase 0 loads: k in [0,256)
            #pragma unroll
            for (int r = 0; r < 16; r++) {
                int idx = t + (r << 8);          // 0..4095
                int rb = idx >> 6, cc = (idx & 63) << 2;
                uint32_t d = (uint32_t)__cvta_generic_to_shared(&hs[rb * HP + cc]);
                asm volatile("cp.async.cg.shared.global [%0], [%1], 16;"
                             :: "r"(d), "l"(hp + ((size_t)rb << 9) + cc));
            }
            asm volatile("cp.async.commit_group;");
            // phase 1 loads: k in [256,512)
            #pragma unroll
            for (int r = 0; r < 16; r++) {
                int idx = t + (r << 8);
                int rb = idx >> 6, cc = ((idx & 63) << 2) + 256;
                uint32_t d = (uint32_t)__cvta_generic_to_shared(&hs[rb * HP + cc]);
                asm volatile("cp.async.cg.shared.global [%0], [%1], 16;"
                             :: "r"(d), "l"(hp + ((size_t)rb << 9) + cc));
            }
            asm volatile("cp.async.commit_group;");

            unsigned long long A0 = 0, A1 = 0, A2 = 0, A3 = 0;
            unsigned long long B0 = 0, B1 = 0, B2 = 0, B3 = 0;

            asm volatile("cp.async.wait_group 1;");
            __syncthreads();
            #pragma unroll 4
            for (int k = 0; k < 256; k += 4) {
                ulonglong2 hv = *(const ulonglong2*)(hb + k);
                ulonglong2 w0 = *(const ulonglong2*)(wp0 + k);
                ulonglong2 w1 = *(const ulonglong2*)(wp1 + k);
                ulonglong2 w2 = *(const ulonglong2*)(wp2 + k);
                ulonglong2 w3 = *(const ulonglong2*)(wp3 + k);
                FMA2(A0, w0.x, hv.x); FMA2(A1, w1.x, hv.x);
                FMA2(A2, w2.x, hv.x); FMA2(A3, w3.x, hv.x);
                FMA2(B0, w0.y, hv.y); FMA2(B1, w1.y, hv.y);
                FMA2(B2, w2.y, hv.y); FMA2(B3, w3.y, hv.y);
            }
            asm volatile("cp.async.wait_group 0;");
            __syncthreads();
            #pragma unroll 4
            for (int k = 256; k < 512; k += 4) {
                ulonglong2 hv = *(const ulonglong2*)(hb + k);
                ulonglong2 w0 = *(const ulonglong2*)(wp0 + k);
                ulonglong2 w1 = *(const ulonglong2*)(wp1 + k);
                ulonglong2 w2 = *(const ulonglong2*)(wp2 + k);
                ulonglong2 w3 = *(const ulonglong2*)(wp3 + k);
                FMA2(A0, w0.x, hv.x); FMA2(A1, w1.x, hv.x);
                FMA2(A2, w2.x, hv.x); FMA2(A3, w3.x, hv.x);
                FMA2(B0, w0.y, hv.y); FMA2(B1, w1.y, hv.y);
                FMA2(B2, w2.y, hv.y); FMA2(B3, w3.y, hv.y);
            }

            a0 += rsum2(A0) + rsum2(B0);
            a1 += rsum2(A1) + rsum2(B1);
            a2 += rsum2(A2) + rsum2(B2);
            a3 += rsum2(A3) + rsum2(B3);
        }

        float ig = 1.f / (1.f + __expf(-a0));
        float fg = 1.f / (1.f + __expf(-a1));
        float gg = tanhf(a2);
        float og = 1.f / (1.f + __expf(-a3));
        c = fg * c + ig * gg;
        float h = og * tanhf(c);
        g_hist[((((size_t)s << 6) + b) << 9) + jg] = h;

        __threadfence();
        __syncthreads();
        if (t == 0) atomicAdd(&g_cnt[s], 1u);
    }
}

// ---------------------------------------------------------------------------
// Output GEMM: out[b][s][f] = sum_j hist[s][b][j]*W_out[f][j] + b_out[f]
// ---------------------------------------------------------------------------
__global__ __launch_bounds__(256) void out_kernel(
    const float* __restrict__ Wout, const float* __restrict__ bout,
    float* __restrict__ out)
{
    __shared__ float As[32][68];
    __shared__ float Bs[32][68];
    const int fBase = blockIdx.x * 64;
    const int mBase = blockIdx.y * 64;
    const int t = threadIdx.x;
    const int tx = t & 15, ty = t >> 4;

    float acc[4][4] = {};

    for (int k0 = 0; k0 < HH; k0 += 32) {
        #pragma unroll
        for (int it = 0; it < 2; it++) {
            int idx = t + it * 256;
            int row = idx >> 3, vec = idx & 7;
            float4 v = *(const float4*)(g_hist + (size_t)(mBase + row) * HH + k0 + vec * 4);
            As[vec * 4 + 0][row] = v.x; As[vec * 4 + 1][row] = v.y;
            As[vec * 4 + 2][row] = v.z; As[vec * 4 + 3][row] = v.w;
        }
        #pragma unroll
        for (int it = 0; it < 2; it++) {
            int idx = t + it * 256;
            int row = idx >> 3, vec = idx & 7;
            float4 v = *(const float4*)(Wout + (size_t)(fBase + row) * HH + k0 + vec * 4);
            Bs[vec * 4 + 0][row] = v.x; Bs[vec * 4 + 1][row] = v.y;
            Bs[vec * 4 + 2][row] = v.z; Bs[vec * 4 + 3][row] = v.w;
        }
        __syncthreads();
        #pragma unroll
        for (int kk = 0; kk < 32; kk++) {
            float a[4], b[4];
            *(float4*)a = *(const float4*)&As[kk][ty * 4];
            *(float4*)b = *(const float4*)&Bs[kk][tx * 4];
            #pragma unroll
            for (int i = 0; i < 4; i++)
                #pragma unroll
                for (int jj = 0; jj < 4; jj++)
                    acc[i][jj] += a[i] * b[jj];
        }
        __syncthreads();
    }

    float bias[4];
    #pragma unroll
    for (int jj = 0; jj < 4; jj++) bias[jj] = bout[fBase + tx * 4 + jj];

    #pragma unroll
    for (int i = 0; i < 4; i++) {
        int m = mBase + ty * 4 + i;
        int b = m & 63, s = m >> 6;
        float4 o;
        o.x = acc[i][0] + bias[0];
        o.y = acc[i][1] + bias[1];
        o.z = acc[i][2] + bias[2];
        o.w = acc[i][3] + bias[3];
        *(float4*)(out + ((size_t)b * SS + s) * FF + fBase + tx * 4) = o;
    }
}

extern "C" void kernel_launch(void* const* d_in, const int* in_sizes, int n_in,
                              void* d_out, int out_size)
{
    const float* inp  = (const float*)d_in[0];
    const float* Wih  = (const float*)d_in[1];
    const float* Whh  = (const float*)d_in[2];
    const float* bih  = (const float*)d_in[3];
    const float* bhh  = (const float*)d_in[4];
    const float* Wout = (const float*)d_in[5];
    const float* bout = (const float*)d_in[6];
    float* out = (float*)d_out;

    const int smem_bytes = (8192 + 64 * HP) * 4;   // 164,864 B
    cudaFuncSetAttribute(lstm_persist,
                         cudaFuncAttributeMaxDynamicSharedMemorySize, smem_bytes);

    init_kernel<<<2, 256>>>();
    xg_kernel<<<dim3(G4 / 64, (SS * BB) / 64), 256>>>(inp, Wih, bih, bhh);
    lstm_persist<<<NCTA, TPB, smem_bytes>>>(Whh);
    out_kernel<<<dim3(FF / 64, (SS * BB) / 64), 256>>>(Wout, bout, out);
}

// round 3
// speedup vs baseline: 2.8424x; 2.8424x over previous
#include <cuda_runtime.h>
#include <math.h>
#include <stdint.h>

#define BB 64
#define SS 512
#define FF 128
#define HH 512
#define G4 2048
#define NCTA 128
#define TPB 512

// Scratch (static device globals — no allocation at kernel_launch time)
__device__ float g_xg[(size_t)SS * G4 * BB];    // [S][4H][B] transposed input gates
__device__ float g_hist[(size_t)SS * BB * HH];  // [S][B][H] hidden state history
__device__ unsigned g_cnt[SS];                  // per-step arrival counters

// packed dual-fp32 FMA (Blackwell f32x2)
#define FMA2(acc, a, h) asm("fma.rn.f32x2 %0, %1, %2, %0;" : "+l"(acc) : "l"(a), "l"(h))

__device__ __forceinline__ float rsum2(unsigned long long v) {
    float lo, hi;
    asm("mov.b64 {%0,%1}, %2;" : "=f"(lo), "=f"(hi) : "l"(v));
    return lo + hi;
}

__global__ void init_kernel() {
    int i = blockIdx.x * blockDim.x + threadIdx.x;
    if (i < SS) g_cnt[i] = 0;
}

// ---------------------------------------------------------------------------
// x_gates GEMM: g_xg[s][g][b] = sum_f inputs[b,s,f]*W_ih[g,f] + b_ih[g]+b_hh[g]
// M = S*B = 32768, N = 2048, K = 128. BM=BN=64 (one s per CTA), 256 thr, 4x4.
// ---------------------------------------------------------------------------
__global__ __launch_bounds__(256) void xg_kernel(
    const float* __restrict__ inp, const float* __restrict__ Wih,
    const float* __restrict__ bih, const float* __restrict__ bhh)
{
    __shared__ float As[32][68];
    __shared__ float Bs[32][68];
    const int gBase = blockIdx.x * 64;
    const int mBase = blockIdx.y * 64;
    const int t = threadIdx.x;
    const int tx = t & 15, ty = t >> 4;

    float acc[4][4] = {};

    for (int k0 = 0; k0 < FF; k0 += 32) {
        #pragma unroll
        for (int it = 0; it < 2; it++) {
            int idx = t + it * 256;
            int row = idx >> 3, vec = idx & 7;
            int m = mBase + row;
            int b = m & 63, s = m >> 6;
            float4 v = *(const float4*)(inp + ((size_t)b * SS + s) * FF + k0 + vec * 4);
            As[vec * 4 + 0][row] = v.x; As[vec * 4 + 1][row] = v.y;
            As[vec * 4 + 2][row] = v.z; As[vec * 4 + 3][row] = v.w;
        }
        #pragma unroll
        for (int it = 0; it < 2; it++) {
            int idx = t + it * 256;
            int row = idx >> 3, vec = idx & 7;
            float4 v = *(const float4*)(Wih + (size_t)(gBase + row) * FF + k0 + vec * 4);
            Bs[vec * 4 + 0][row] = v.x; Bs[vec * 4 + 1][row] = v.y;
            Bs[vec * 4 + 2][row] = v.z; Bs[vec * 4 + 3][row] = v.w;
        }
        __syncthreads();
        #pragma unroll
        for (int kk = 0; kk < 32; kk++) {
            float a[4], b[4];
            *(float4*)a = *(const float4*)&As[kk][ty * 4];
            *(float4*)b = *(const float4*)&Bs[kk][tx * 4];
            #pragma unroll
            for (int i = 0; i < 4; i++)
                #pragma unroll
                for (int jj = 0; jj < 4; jj++)
                    acc[i][jj] += a[i] * b[jj];
        }
        __syncthreads();
    }

    const int s = mBase >> 6;   // one s per CTA (mBase multiple of 64)
    #pragma unroll
    for (int jj = 0; jj < 4; jj++) {
        int g = gBase + tx * 4 + jj;
        float bias = bih[g] + bhh[g];
        float4 o;
        o.x = acc[0][jj] + bias;
        o.y = acc[1][jj] + bias;
        o.z = acc[2][jj] + bias;
        o.w = acc[3][jj] + bias;
        // b = ty*4..ty*4+3 consecutive
        *(float4*)(g_xg + ((size_t)(s * G4 + g) << 6) + ty * 4) = o;
    }
}

// ---------------------------------------------------------------------------
// Persistent LSTM. 128 CTAs = 32 j-groups x 4 b-groups, tile 16 units x 16 b.
// W slice (64 rows x 512, XOR-swizzled) in SMEM. Per step: grid barrier,
// h tile (16 x 512) via cp.async, 4-way k-split compute, SMEM reduction.
// SMEM floats: ws 32768 | hs 16*516 | xg2 2*1024 | red 4*4*16*16
// ---------------------------------------------------------------------------
#define SM_WS   0
#define SM_HS   32768
#define SM_XG   41024
#define SM_RED  43072
#define SM_TOT  47168

__global__ __launch_bounds__(TPB, 1) void lstm_persist(const float* __restrict__ Whh)
{
    extern __shared__ float sm[];
    float* ws  = sm + SM_WS;
    float* hs  = sm + SM_HS;
    float* xg2 = sm + SM_XG;
    float* red = sm + SM_RED;

    const int t = threadIdx.x;
    const int w = t >> 5, l = t & 31;
    const int jg0 = (blockIdx.x >> 2) << 4;    // j group base (32 groups)
    const int b0  = (blockIdx.x & 3) << 4;     // b group base (4 groups)

    // compute-role decode: thread = (kq, jl, bp); 4 gates x 2 b x 128 k each
    const int kq = w >> 2;                     // 0..3
    const int jl = ((w & 3) << 2) + (l >> 3);  // 0..15
    const int bp = l & 7;                      // 0..7
    const int k0 = kq << 7;

    // Load W slice: ws[row][.] , row = jl*4 + g ; granule swizzle ^= (row>>2)&7
    for (int i = t; i < 64 * 128; i += TPB) {
        int row = i >> 7, g16 = i & 127;
        int jr = row >> 2, gr = row & 3;
        int pg = g16 ^ ((row >> 2) & 7);
        *(float4*)&ws[(row << 9) + (pg << 2)] =
            *(const float4*)&Whh[((size_t)(gr * HH + jg0 + jr) << 9) + (g16 << 2)];
    }

    // Prefetch xg(0) into buffer 0 (warps 0-7)
    if (t < 256) {
        int row = t >> 2, q = t & 3;           // row = g*16+j (64 rows x 64B)
        int g = row >> 4, j = row & 15;
        const float* src = g_xg + ((size_t)(g * HH + jg0 + j) << 6) + b0 + (q << 2);
        uint32_t d = (uint32_t)__cvta_generic_to_shared(&xg2[(row << 4) + (q << 2)]);
        asm volatile("cp.async.cg.shared.global [%0], [%1], 16;" :: "r"(d), "l"(src));
        asm volatile("cp.async.commit_group;");
    }
    __syncthreads();

    const float* hrow0 = hs + bp * 516;
    const float* hrow1 = hs + (bp + 8) * 516;
    const int rbase = jl << 2;
    const float* wp0 = ws + ((rbase + 0) << 9);
    const float* wp1 = ws + ((rbase + 1) << 9);
    const float* wp2 = ws + ((rbase + 2) << 9);
    const float* wp3 = ws + ((rbase + 3) << 9);
    const int xr = (jl & 7) << 2;              // shared xor offset (floats)

    const int jo = t & 15, bo = (t >> 4) & 15; // owner decode (t < 256)
    float c = 0.f;

    for (int s = 0; s < SS; s++) {
        // Prefetch xg(s+1) (warps 0-7, own commit group)
        if (t < 256 && s + 1 < SS) {
            int row = t >> 2, q = t & 3;
            int g = row >> 4, j = row & 15;
            const float* src = g_xg +
                ((size_t)((s + 1) * G4 + g * HH + jg0 + j) << 6) + b0 + (q << 2);
            uint32_t d = (uint32_t)__cvta_generic_to_shared(
                &xg2[(((s + 1) & 1) << 10) + (row << 4) + (q << 2)]);
            asm volatile("cp.async.cg.shared.global [%0], [%1], 16;" :: "r"(d), "l"(src));
            asm volatile("cp.async.commit_group;");
        }

        if (s > 0) {
            if (t == 0) {
                unsigned v;
                do {
                    asm volatile("ld.acquire.gpu.global.u32 %0, [%1];"
                                 : "=r"(v) : "l"(g_cnt + (s - 1)) : "memory");
                } while (v < NCTA);
            }
            __syncthreads();

            // h tile load: warps 0-7 -> k[0,256), warps 8-15 -> k[256,512)
            {
                const float* hp = g_hist + ((size_t)(s - 1) << 15);
                int u = t & 255;
                int cofs = (t < 256) ? 0 : 64;
                #pragma unroll
                for (int it = 0; it < 4; it++) {
                    int gidx = u + (it << 8);              // 0..1023
                    int r = gidx >> 6, c16 = (gidx & 63) + cofs;
                    uint32_t d = (uint32_t)__cvta_generic_to_shared(
                        &hs[r * 516 + (c16 << 2)]);
                    asm volatile("cp.async.cg.shared.global [%0], [%1], 16;"
                                 :: "r"(d),
                                    "l"(hp + (((size_t)(b0 + r)) << 9) + (c16 << 2)));
                }
                asm volatile("cp.async.commit_group;");
                asm volatile("cp.async.wait_group 0;");
            }
            if (t < 256) asm volatile("bar.sync 1, 256;");
            else         asm volatile("bar.sync 2, 256;");

            // compute: 4 gates x 2 b over k0..k0+127
            unsigned long long A00 = 0, A01 = 0, A10 = 0, A11 = 0;
            unsigned long long A20 = 0, A21 = 0, A30 = 0, A31 = 0;
            #pragma unroll 4
            for (int k = k0; k < k0 + 128; k += 4) {
                int kx = k ^ xr;
                ulonglong2 hv0 = *(const ulonglong2*)(hrow0 + k);
                ulonglong2 hv1 = *(const ulonglong2*)(hrow1 + k);
                ulonglong2 w0 = *(const ulonglong2*)(wp0 + kx);
                ulonglong2 w1 = *(const ulonglong2*)(wp1 + kx);
                ulonglong2 w2 = *(const ulonglong2*)(wp2 + kx);
                ulonglong2 w3 = *(const ulonglong2*)(wp3 + kx);
                FMA2(A00, w0.x, hv0.x); FMA2(A10, w1.x, hv0.x);
                FMA2(A20, w2.x, hv0.x); FMA2(A30, w3.x, hv0.x);
                FMA2(A01, w0.x, hv1.x); FMA2(A11, w1.x, hv1.x);
                FMA2(A21, w2.x, hv1.x); FMA2(A31, w3.x, hv1.x);
                FMA2(A00, w0.y, hv0.y); FMA2(A10, w1.y, hv0.y);
                FMA2(A20, w2.y, hv0.y); FMA2(A30, w3.y, hv0.y);
                FMA2(A01, w0.y, hv1.y); FMA2(A11, w1.y, hv1.y);
                FMA2(A21, w2.y, hv1.y); FMA2(A31, w3.y, hv1.y);
            }
            // partials -> red[kq][g][b][j]
            const int rb = (kq << 10) + (bp << 4) + jl;       // (kq*4+g)*256 + b*16 + j
            red[rb          ] = rsum2(A00);
            red[rb + 128    ] = rsum2(A01);
            red[rb + 256    ] = rsum2(A10);
            red[rb + 256+128] = rsum2(A11);
            red[rb + 512    ] = rsum2(A20);
            red[rb + 512+128] = rsum2(A21);
            red[rb + 768    ] = rsum2(A30);
            red[rb + 768+128] = rsum2(A31);
        } else {
            // make xg(0) visible before owner phase
            if (t < 256) asm volatile("cp.async.wait_group 1;");
        }
        __syncthreads();

        if (t < 256) {
            const float* xb = xg2 + ((s & 1) << 10);
            float a0 = xb[((0 * 16 + jo) << 4) + bo];
            float a1 = xb[((1 * 16 + jo) << 4) + bo];
            float a2 = xb[((2 * 16 + jo) << 4) + bo];
            float a3 = xb[((3 * 16 + jo) << 4) + bo];
            if (s > 0) {
                const int ro = (bo << 4) + jo;
                #pragma unroll
                for (int q = 0; q < 4; q++) {
                    a0 += red[(q << 10)        + ro];
                    a1 += red[(q << 10) + 256  + ro];
                    a2 += red[(q << 10) + 512  + ro];
                    a3 += red[(q << 10) + 768  + ro];
                }
            }
            float ig = 1.f / (1.f + __expf(-a0));
            float fg = 1.f / (1.f + __expf(-a1));
            float gg = tanhf(a2);
            float og = 1.f / (1.f + __expf(-a3));
            c = fg * c + ig * gg;
            float h = og * tanhf(c);
            g_hist[(((size_t)(s << 6) + b0 + bo) << 9) + jg0 + jo] = h;
        }
        __syncthreads();
        if (t == 0)
            asm volatile("red.release.gpu.global.add.u32 [%0], %1;"
                         :: "l"(g_cnt + s), "r"(1u) : "memory");
    }
}

// ---------------------------------------------------------------------------
// Output GEMM: out[b][s][f] = sum_j hist[s][b][j]*W_out[f][j] + b_out[f]
// ---------------------------------------------------------------------------
__global__ __launch_bounds__(256) void out_kernel(
    const float* __restrict__ Wout, const float* __restrict__ bout,
    float* __restrict__ out)
{
    __shared__ float As[32][68];
    __shared__ float Bs[32][68];
    const int fBase = blockIdx.x * 64;
    const int mBase = blockIdx.y * 64;
    const int t = threadIdx.x;
    const int tx = t & 15, ty = t >> 4;

    float acc[4][4] = {};

    for (int k0 = 0; k0 < HH; k0 += 32) {
        #pragma unroll
        for (int it = 0; it < 2; it++) {
            int idx = t + it * 256;
            int row = idx >> 3, vec = idx & 7;
            float4 v = *(const float4*)(g_hist + (size_t)(mBase + row) * HH + k0 + vec * 4);
            As[vec * 4 + 0][row] = v.x; As[vec * 4 + 1][row] = v.y;
            As[vec * 4 + 2][row] = v.z; As[vec * 4 + 3][row] = v.w;
        }
        #pragma unroll
        for (int it = 0; it < 2; it++) {
            int idx = t + it * 256;
            int row = idx >> 3, vec = idx & 7;
            float4 v = *(const float4*)(Wout + (size_t)(fBase + row) * HH + k0 + vec * 4);
            Bs[vec * 4 + 0][row] = v.x; Bs[vec * 4 + 1][row] = v.y;
            Bs[vec * 4 + 2][row] = v.z; Bs[vec * 4 + 3][row] = v.w;
        }
        __syncthreads();
        #pragma unroll
        for (int kk = 0; kk < 32; kk++) {
            float a[4], b[4];
            *(float4*)a = *(const float4*)&As[kk][ty * 4];
            *(float4*)b = *(const float4*)&Bs[kk][tx * 4];
            #pragma unroll
            for (int i = 0; i < 4; i++)
                #pragma unroll
                for (int jj = 0; jj < 4; jj++)
                    acc[i][jj] += a[i] * b[jj];
        }
        __syncthreads();
    }

    float bias[4];
    #pragma unroll
    for (int jj = 0; jj < 4; jj++) bias[jj] = bout[fBase + tx * 4 + jj];

    #pragma unroll
    for (int i = 0; i < 4; i++) {
        int m = mBase + ty * 4 + i;
        int b = m & 63, s = m >> 6;
        float4 o;
        o.x = acc[i][0] + bias[0];
        o.y = acc[i][1] + bias[1];
        o.z = acc[i][2] + bias[2];
        o.w = acc[i][3] + bias[3];
        *(float4*)(out + ((size_t)b * SS + s) * FF + fBase + tx * 4) = o;
    }
}

extern "C" void kernel_launch(void* const* d_in, const int* in_sizes, int n_in,
                              void* d_out, int out_size)
{
    const float* inp  = (const float*)d_in[0];
    const float* Wih  = (const float*)d_in[1];
    const float* Whh  = (const float*)d_in[2];
    const float* bih  = (const float*)d_in[3];
    const float* bhh  = (const float*)d_in[4];
    const float* Wout = (const float*)d_in[5];
    const float* bout = (const float*)d_in[6];
    float* out = (float*)d_out;

    const int smem_bytes = SM_TOT * 4;  // 188,672 B
    cudaFuncSetAttribute(lstm_persist,
                         cudaFuncAttributeMaxDynamicSharedMemorySize, smem_bytes);

    init_kernel<<<2, 256>>>();
    xg_kernel<<<dim3(G4 / 64, (SS * BB) / 64), 256>>>(inp, Wih, bih, bhh);
    lstm_persist<<<NCTA, TPB, smem_bytes>>>(Whh);
    out_kernel<<<dim3(FF / 64, (SS * BB) / 64), 256>>>(Wout, bout, out);
}

// round 6
// speedup vs baseline: 3.4209x; 1.2035x over previous
#include <cuda_runtime.h>
#include <math.h>
#include <stdint.h>

#define BB 64
#define SS 512
#define FF 128
#define HH 512
#define G4 2048
#define NCTA 128
#define NCTAG 32          // CTAs per b-group barrier
#define TPB 512

// Scratch (static device globals — no allocation at kernel_launch time)
__device__ float g_xg[(size_t)SS * BB * G4];    // [S][B][4H] input gates
__device__ float g_hist[(size_t)SS * BB * HH];  // [S][B][H] hidden states
__device__ unsigned g_cnt[4 * SS];              // per-(bgroup,step) counters

// packed dual-fp32 FMA (Blackwell f32x2)
#define FMA2(acc, a, h) asm("fma.rn.f32x2 %0, %1, %2, %0;" : "+l"(acc) : "l"(a), "l"(h))

__device__ __forceinline__ float rsum2(unsigned long long v) {
    float lo, hi;
    asm("mov.b64 {%0,%1}, %2;" : "=f"(lo), "=f"(hi) : "l"(v));
    return lo + hi;
}

#define CP16(dst, src) asm volatile("cp.async.cg.shared.global [%0], [%1], 16;" \
                                    :: "r"(dst), "l"(src))

__global__ void init_kernel() {
    int i = blockIdx.x * blockDim.x + threadIdx.x;
    if (i < 4 * SS) g_cnt[i] = 0;
}

// ---------------------------------------------------------------------------
// x_gates GEMM: g_xg[m][g] = sum_f inputs[b,s,f]*W_ih[g,f] + b_ih[g]+b_hh[g]
// m = s*64+b. M=32768, N=2048, K=128. BM=BN=128, BK=16, 256 thr, 8x8, FMA2.
// ---------------------------------------------------------------------------
__global__ __launch_bounds__(256) void xg_kernel(
    const float* __restrict__ inp, const float* __restrict__ Wih,
    const float* __restrict__ bih, const float* __restrict__ bhh)
{
    __shared__ float As[16][132];
    __shared__ float Bs[16][132];
    const int gBase = blockIdx.x * 128;
    const int mBase = blockIdx.y * 128;
    const int t = threadIdx.x;
    const int tx = t & 15, ty = t >> 4;

    unsigned long long acc[8][4];
    #pragma unroll
    for (int i = 0; i < 8; i++)
        #pragma unroll
        for (int j = 0; j < 4; j++) acc[i][j] = 0ull;

    for (int k0 = 0; k0 < FF; k0 += 16) {
        #pragma unroll
        for (int it = 0; it < 2; it++) {
            int idx = t + (it << 8);
            int row = idx >> 2, c4 = idx & 3;
            int m = mBase + row;
            int b = m & 63, s = m >> 6;
            float4 v = *(const float4*)(inp + ((size_t)b * SS + s) * FF + k0 + (c4 << 2));
            As[c4 * 4 + 0][row] = v.x; As[c4 * 4 + 1][row] = v.y;
            As[c4 * 4 + 2][row] = v.z; As[c4 * 4 + 3][row] = v.w;
        }
        #pragma unroll
        for (int it = 0; it < 2; it++) {
            int idx = t + (it << 8);
            int row = idx >> 2, c4 = idx & 3;
            float4 v = *(const float4*)(Wih + (size_t)(gBase + row) * FF + k0 + (c4 << 2));
            Bs[c4 * 4 + 0][row] = v.x; Bs[c4 * 4 + 1][row] = v.y;
            Bs[c4 * 4 + 2][row] = v.z; Bs[c4 * 4 + 3][row] = v.w;
        }
        __syncthreads();
        #pragma unroll
        for (int kk = 0; kk < 16; kk++) {
            float a[8];
            *(float4*)(a)     = *(const float4*)&As[kk][ty * 8];
            *(float4*)(a + 4) = *(const float4*)&As[kk][ty * 8 + 4];
            ulonglong2 b01 = *(const ulonglong2*)&Bs[kk][tx * 8];
            ulonglong2 b23 = *(const ulonglong2*)&Bs[kk][tx * 8 + 4];
            #pragma unroll
            for (int i = 0; i < 8; i++) {
                unsigned long long a2;
                asm("mov.b64 %0, {%1, %1};" : "=l"(a2) : "f"(a[i]));
                FMA2(acc[i][0], a2, b01.x);
                FMA2(acc[i][1], a2, b01.y);
                FMA2(acc[i][2], a2, b23.x);
                FMA2(acc[i][3], a2, b23.y);
            }
        }
        __syncthreads();
    }

    float bias[8];
    #pragma unroll
    for (int j = 0; j < 8; j++) {
        int g = gBase + tx * 8 + j;
        bias[j] = bih[g] + bhh[g];
    }
    #pragma unroll
    for (int i = 0; i < 8; i++) {
        int m = mBase + ty * 8 + i;
        float f[8];
        #pragma unroll
        for (int jp = 0; jp < 4; jp++)
            asm("mov.b64 {%0,%1}, %2;" : "=f"(f[2*jp]), "=f"(f[2*jp+1]) : "l"(acc[i][jp]));
        float4 o0, o1;
        o0.x = f[0] + bias[0]; o0.y = f[1] + bias[1];
        o0.z = f[2] + bias[2]; o0.w = f[3] + bias[3];
        o1.x = f[4] + bias[4]; o1.y = f[5] + bias[5];
        o1.z = f[6] + bias[6]; o1.w = f[7] + bias[7];
        *(float4*)(g_xg + (size_t)m * G4 + gBase + tx * 8)     = o0;
        *(float4*)(g_xg + (size_t)m * G4 + gBase + tx * 8 + 4) = o1;
    }
}

// ---------------------------------------------------------------------------
// Persistent LSTM. 128 CTAs = 32 j-groups x 4 b-groups (independent barriers).
// Thread = (kq in 8, jl in 16, bq in 4): 4 gates x 4 batches x 64 k.
// SMEM (floats): ws 32768 | hs 16x516 | xg2 2x1024 | red 256x33
// ---------------------------------------------------------------------------
#define SM_HS   32768
#define SM_XG   41024
#define SM_RED  43072
#define SM_TOT  51520

__global__ __launch_bounds__(TPB, 1) void lstm_persist(const float* __restrict__ Whh)
{
    extern __shared__ float sm[];
    float* ws  = sm;
    float* hs  = sm + SM_HS;
    float* xg2 = sm + SM_XG;
    float* red = sm + SM_RED;

    const int t = threadIdx.x;
    const int w = t >> 5, l = t & 31;
    const int jg0  = (blockIdx.x >> 2) << 4;
    const int bgrp = blockIdx.x & 3;
    const int b0   = bgrp << 4;

    const int kq = w >> 1;                     // 0..7
    const int jl = (l & 7) | ((w & 1) << 3);   // 0..15
    const int bq = l >> 3;                     // 0..3
    const int k0 = kq << 6;
    const int k0w = k0 + ((w & 1) << 5);       // this warp's 32-col h slice

    // Load W slice once: ws[row=jl*4+g][k], granule swizzle ^(jl&7)
    for (int i = t; i < 64 * 128; i += TPB) {
        int row = i >> 7, g16 = i & 127;
        int jr = row >> 2, gr = row & 3;
        int pg = g16 ^ (jr & 7);
        *(float4*)&ws[(row << 9) + (pg << 2)] =
            *(const float4*)&Whh[((size_t)(gr * HH + jg0 + jr) << 9) + (g16 << 2)];
    }

    // Prefetch xg(0): thread (bi,g,j4) -> xg2[(g*16+bi)*16 + j4*4]
    if (t < 256) {
        int bi = t >> 4, cc = t & 15;
        int g = cc >> 2, j4 = cc & 3;
        const float* src = g_xg + (size_t)(b0 + bi) * G4 + g * HH + jg0 + (j4 << 2);
        uint32_t d = (uint32_t)__cvta_generic_to_shared(
            &xg2[((g << 4) + bi) * 16 + (j4 << 2)]);
        CP16(d, src);
        asm volatile("cp.async.commit_group;");
    }
    __syncthreads();

    const float* wq0 = ws + ((jl * 4 + 0) << 9);
    const float* wq1 = ws + ((jl * 4 + 1) << 9);
    const float* wq2 = ws + ((jl * 4 + 2) << 9);
    const float* wq3 = ws + ((jl * 4 + 3) << 9);
    const int xr = (jl & 7) << 2;

    float c = 0.f;

    for (int s = 0; s < SS; s++) {
        // Prefetch xg(s+1)
        if (t < 256 && s + 1 < SS) {
            int bi = t >> 4, cc = t & 15;
            int g = cc >> 2, j4 = cc & 3;
            const float* src = g_xg +
                (size_t)((s + 1) * BB + b0 + bi) * G4 + g * HH + jg0 + (j4 << 2);
            uint32_t d = (uint32_t)__cvta_generic_to_shared(
                &xg2[(((s + 1) & 1) << 10) + ((g << 4) + bi) * 16 + (j4 << 2)]);
            CP16(d, src);
            asm volatile("cp.async.commit_group;");
        }

        if (s > 0) {
            if (t == 0) {
                unsigned v;
                const unsigned* ca = g_cnt + bgrp * SS + (s - 1);
                do {
                    asm volatile("ld.acquire.gpu.global.u32 %0, [%1];"
                                 : "=r"(v) : "l"(ca) : "memory");
                } while (v < NCTAG);
            }
            __syncthreads();

            // per-warp h slice: 16 batches x 32 k-cols
            {
                const float* hp = g_hist + ((size_t)(s - 1) << 15);
                #pragma unroll
                for (int it = 0; it < 4; it++) {
                    int idx = (it << 5) + l;
                    int r = idx >> 3, c4 = idx & 7;
                    int col = k0w + (c4 << 2);
                    uint32_t d = (uint32_t)__cvta_generic_to_shared(&hs[r * 516 + col]);
                    CP16(d, hp + (((size_t)(b0 + r)) << 9) + col);
                }
                asm volatile("cp.async.commit_group;");
                asm volatile("cp.async.wait_group 0;");
                asm volatile("bar.sync %0, 64;" :: "r"(kq + 1));
            }

            unsigned long long A0[4], A1[4], A2[4], A3[4];
            #pragma unroll
            for (int i = 0; i < 4; i++) { A0[i] = 0; A1[i] = 0; A2[i] = 0; A3[i] = 0; }

            #pragma unroll 4
            for (int k = k0; k < k0 + 64; k += 4) {
                int kx = k ^ xr;
                ulonglong2 w0 = *(const ulonglong2*)(wq0 + kx);
                ulonglong2 w1 = *(const ulonglong2*)(wq1 + kx);
                ulonglong2 w2 = *(const ulonglong2*)(wq2 + kx);
                ulonglong2 w3 = *(const ulonglong2*)(wq3 + kx);
                #pragma unroll
                for (int i = 0; i < 4; i++) {
                    ulonglong2 hv = *(const ulonglong2*)(hs + (i * 4 + bq) * 516 + k);
                    FMA2(A0[i], w0.x, hv.x); FMA2(A0[i], w0.y, hv.y);
                    FMA2(A1[i], w1.x, hv.x); FMA2(A1[i], w1.y, hv.y);
                    FMA2(A2[i], w2.x, hv.x); FMA2(A2[i], w2.y, hv.y);
                    FMA2(A3[i], w3.x, hv.x); FMA2(A3[i], w3.y, hv.y);
                }
            }
            // partials: red[(b*16+j)*33 + kq*4+g]
            const int rr = kq << 2;
            #pragma unroll
            for (int i = 0; i < 4; i++) {
                int base = ((i * 4 + bq) * 16 + jl) * 33 + rr;
                red[base + 0] = rsum2(A0[i]);
                red[base + 1] = rsum2(A1[i]);
                red[base + 2] = rsum2(A2[i]);
                red[base + 3] = rsum2(A3[i]);
            }
        } else {
            if (t < 256) asm volatile("cp.async.wait_group 1;");
        }
        __syncthreads();

        if (t < 256) {
            const int jo = t & 15, bo = t >> 4;
            const float* xb = xg2 + ((s & 1) << 10);
            float a0 = xb[       (bo << 4) + jo];
            float a1 = xb[256 +  (bo << 4) + jo];
            float a2 = xb[512 +  (bo << 4) + jo];
            float a3 = xb[768 +  (bo << 4) + jo];
            if (s > 0) {
                const float* rp = red + ((bo << 4) + jo) * 33;
                #pragma unroll
                for (int q = 0; q < 8; q++) {
                    a0 += rp[q * 4 + 0];
                    a1 += rp[q * 4 + 1];
                    a2 += rp[q * 4 + 2];
                    a3 += rp[q * 4 + 3];
                }
            }
            float ig = 1.f / (1.f + __expf(-a0));
            float fg = 1.f / (1.f + __expf(-a1));
            float gg = 2.f / (1.f + __expf(-2.f * a2)) - 1.f;
            float og = 1.f / (1.f + __expf(-a3));
            c = fg * c + ig * gg;
            float th = 2.f / (1.f + __expf(-2.f * c)) - 1.f;
            g_hist[((size_t)(s * BB + b0 + bo) << 9) + jg0 + jo] = og * th;
        }
        __syncthreads();
        if (t == 0)
            asm volatile("red.release.gpu.global.add.u32 [%0], %1;"
                         :: "l"(g_cnt + bgrp * SS + s), "r"(1u) : "memory");
    }
}

// ---------------------------------------------------------------------------
// Output GEMM: out[b][s][f] = sum_j hist[s][b][j]*W_out[f][j] + b_out[f]
// ---------------------------------------------------------------------------
__global__ __launch_bounds__(256) void out_kernel(
    const float* __restrict__ Wout, const float* __restrict__ bout,
    float* __restrict__ out)
{
    __shared__ float As[32][68];
    __shared__ float Bs[32][68];
    const int fBase = blockIdx.x * 64;
    const int mBase = blockIdx.y * 64;
    const int t = threadIdx.x;
    const int tx = t & 15, ty = t >> 4;

    float acc[4][4] = {};

    for (int k0 = 0; k0 < HH; k0 += 32) {
        #pragma unroll
        for (int it = 0; it < 2; it++) {
            int idx = t + it * 256;
            int row = idx >> 3, vec = idx & 7;
            float4 v = *(const float4*)(g_hist + (size_t)(mBase + row) * HH + k0 + vec * 4);
            As[vec * 4 + 0][row] = v.x; As[vec * 4 + 1][row] = v.y;
            As[vec * 4 + 2][row] = v.z; As[vec * 4 + 3][row] = v.w;
        }
        #pragma unroll
        for (int it = 0; it < 2; it++) {
            int idx = t + it * 256;
            int row = idx >> 3, vec = idx & 7;
            float4 v = *(const float4*)(Wout + (size_t)(fBase + row) * HH + k0 + vec * 4);
            Bs[vec * 4 + 0][row] = v.x; Bs[vec * 4 + 1][row] = v.y;
            Bs[vec * 4 + 2][row] = v.z; Bs[vec * 4 + 3][row] = v.w;
        }
        __syncthreads();
        #pragma unroll
        for (int kk = 0; kk < 32; kk++) {
            float a[4], b[4];
            *(float4*)a = *(const float4*)&As[kk][ty * 4];
            *(float4*)b = *(const float4*)&Bs[kk][tx * 4];
            #pragma unroll
            for (int i = 0; i < 4; i++)
                #pragma unroll
                for (int jj = 0; jj < 4; jj++)
                    acc[i][jj] += a[i] * b[jj];
        }
        __syncthreads();
    }

    float bias[4];
    #pragma unroll
    for (int jj = 0; jj < 4; jj++) bias[jj] = bout[fBase + tx * 4 + jj];

    #pragma unroll
    for (int i = 0; i < 4; i++) {
        int m = mBase + ty * 4 + i;
        int b = m & 63, s = m >> 6;
        float4 o;
        o.x = acc[i][0] + bias[0];
        o.y = acc[i][1] + bias[1];
        o.z = acc[i][2] + bias[2];
        o.w = acc[i][3] + bias[3];
        *(float4*)(out + ((size_t)b * SS + s) * FF + fBase + tx * 4) = o;
    }
}

extern "C" void kernel_launch(void* const* d_in, const int* in_sizes, int n_in,
                              void* d_out, int out_size)
{
    const float* inp  = (const float*)d_in[0];
    const float* Wih  = (const float*)d_in[1];
    const float* Whh  = (const float*)d_in[2];
    const float* bih  = (const float*)d_in[3];
    const float* bhh  = (const float*)d_in[4];
    const float* Wout = (const float*)d_in[5];
    const float* bout = (const float*)d_in[6];
    float* out = (float*)d_out;

    const int smem_bytes = SM_TOT * 4;  // 206,080 B
    cudaFuncSetAttribute(lstm_persist,
                         cudaFuncAttributeMaxDynamicSharedMemorySize, smem_bytes);

    init_kernel<<<8, 256>>>();
    xg_kernel<<<dim3(G4 / 128, (SS * BB) / 128), 256>>>(inp, Wih, bih, bhh);
    lstm_persist<<<NCTA, TPB, smem_bytes>>>(Whh);
    out_kernel<<<dim3(FF / 64, (SS * BB) / 64), 256>>>(Wout, bout, out);
}